// round 10
// baseline (speedup 1.0000x reference)
#include <cuda_runtime.h>
#include <cuda_bf16.h>

// DynamicPatchAggregator — gather, float4 along w, FULL 3-axis region
// specialization. Each axis splits into coverage classes:
//   [0,48) u [144,192) -> 1 covering patch (96 coords),
//   [48,144)           -> 2 covering patches (96 coords).
// 8 (nd,nh,nw) classes selected by blockIdx.z; every block runs one
// fully-specialized straight-line path with ZERO dead loads or dead FMAs.
// vol=192^3, patch=96^3, stride=48 -> starts {0,48,96}, 27 patches, C=2.
// Coverage complete -> upsampled global branch contributes 0; skipped.

#define VOL 192
#define PATCH 96
#define STRIDE 48
#define CH_STRIDE (PATCH*PATCH*PATCH)          // 884736
#define PATCH_STRIDE (2*CH_STRIDE)             // per-k stride (C=2)
#define OUT_CH_STRIDE (VOL*VOL*VOL)            // 7077888

__device__ __forceinline__ float gweight(int l) {
    float t = (float)(l - 48) * (1.0f / 12.0f);
    return __expf(-0.5f * t * t);
}

template<int ND, int NH, int NW>
__device__ __forceinline__ void region_body(const float* __restrict__ patch,
                                            float* __restrict__ out,
                                            int d, int h, int w0) {
    // d axis
    const int lod = max((d - 48) / 48, 0);
    const int ld0 = d - lod * STRIDE;
    float gd[2]; int offD[2];
    gd[0]  = gweight(ld0);
    offD[0] = lod * (9 * PATCH_STRIDE) + ld0 * (PATCH * PATCH);
    if (ND == 2) {
        gd[1]  = gweight(ld0 - STRIDE);
        offD[1] = offD[0] + 9 * PATCH_STRIDE - STRIDE * (PATCH * PATCH);
    }

    // h axis
    const int loh = max((h - 48) / 48, 0);
    const int lh0 = h - loh * STRIDE;
    float gh[2]; int offH[2];
    gh[0]  = gweight(lh0);
    offH[0] = loh * (3 * PATCH_STRIDE) + lh0 * PATCH;
    if (NH == 2) {
        gh[1]  = gweight(lh0 - STRIDE);
        offH[1] = offH[0] + 3 * PATCH_STRIDE - STRIDE * PATCH;
    }

    // w axis (compile-time NW)
    const int wlo = max((w0 - 48) / 48, 0);
    const int wl0 = w0 - wlo * STRIDE;
    int offW[2];
    offW[0] = wlo * PATCH_STRIDE + wl0;
    float gw[2][4], gsw[4];
    #pragma unroll
    for (int j = 0; j < 4; j++) {
        gw[0][j] = gweight(wl0 + j);
        gsw[j] = gw[0][j];
    }
    if (NW == 2) {
        offW[1] = offW[0] + PATCH_STRIDE - STRIDE;
        #pragma unroll
        for (int j = 0; j < 4; j++) {
            gw[1][j] = gweight(wl0 - STRIDE + j);
            gsw[j] += gw[1][j];
        }
    }

    float4 acc0 = make_float4(0.f, 0.f, 0.f, 0.f);
    float4 acc1 = make_float4(0.f, 0.f, 0.f, 0.f);

    #pragma unroll
    for (int id = 0; id < ND; id++) {
        #pragma unroll
        for (int ih = 0; ih < NH; ih++) {
            const float gdh = gd[id] * gh[ih];
            const int offDH = offD[id] + offH[ih];
            #pragma unroll
            for (int iw = 0; iw < NW; iw++) {
                const float* q = patch + offDH + offW[iw];
                const float4 v0 = __ldcs(reinterpret_cast<const float4*>(q));
                const float4 v1 = __ldcs(reinterpret_cast<const float4*>(q + CH_STRIDE));
                acc0.x = fmaf(gdh * gw[iw][0], v0.x, acc0.x);
                acc0.y = fmaf(gdh * gw[iw][1], v0.y, acc0.y);
                acc0.z = fmaf(gdh * gw[iw][2], v0.z, acc0.z);
                acc0.w = fmaf(gdh * gw[iw][3], v0.w, acc0.w);
                acc1.x = fmaf(gdh * gw[iw][0], v1.x, acc1.x);
                acc1.y = fmaf(gdh * gw[iw][1], v1.y, acc1.y);
                acc1.z = fmaf(gdh * gw[iw][2], v1.z, acc1.z);
                acc1.w = fmaf(gdh * gw[iw][3], v1.w, acc1.w);
            }
        }
    }

    const float gdsum = (ND == 2) ? gd[0] + gd[1] : gd[0];
    const float ghsum = (NH == 2) ? gh[0] + gh[1] : gh[0];
    const float gdsh = gdsum * ghsum;
    float4 inv;
    inv.x = __frcp_rn(fmaf(gdsh, gsw[0], 1e-20f));
    inv.y = __frcp_rn(fmaf(gdsh, gsw[1], 1e-20f));
    inv.z = __frcp_rn(fmaf(gdsh, gsw[2], 1e-20f));
    inv.w = __frcp_rn(fmaf(gdsh, gsw[3], 1e-20f));

    acc0.x *= inv.x; acc0.y *= inv.y; acc0.z *= inv.z; acc0.w *= inv.w;
    acc1.x *= inv.x; acc1.y *= inv.y; acc1.z *= inv.z; acc1.w *= inv.w;

    const int vidx = (d * VOL + h) * VOL + w0;
    __stcs(reinterpret_cast<float4*>(out + vidx), acc0);
    __stcs(reinterpret_cast<float4*>(out + vidx + OUT_CH_STRIDE), acc1);
}

__global__ __launch_bounds__(192, 6) void agg_kernel_r8(const float* __restrict__ patch,
                                                        float* __restrict__ out) {
    const int wr = threadIdx.x * 4;                 // 0..92 region-local w
    const int hr = blockIdx.x * 8 + threadIdx.y;    // 0..95 region-local h
    const int dr = blockIdx.y;                      // 0..95 region-local d

    // split-class mapping: class 1 (n=1): [0,48)u[144,192); class 2: +48
    const int w1 = (wr < 48) ? wr : wr + 96;
    const int h1 = (hr < 48) ? hr : hr + 96;
    const int d1 = (dr < 48) ? dr : dr + 96;
    const int w2 = wr + 48, h2 = hr + 48, d2 = dr + 48;

    switch (blockIdx.z) {
        case 0: region_body<1,1,1>(patch, out, d1, h1, w1); break;
        case 1: region_body<1,1,2>(patch, out, d1, h1, w2); break;
        case 2: region_body<1,2,1>(patch, out, d1, h2, w1); break;
        case 3: region_body<1,2,2>(patch, out, d1, h2, w2); break;
        case 4: region_body<2,1,1>(patch, out, d2, h1, w1); break;
        case 5: region_body<2,1,2>(patch, out, d2, h1, w2); break;
        case 6: region_body<2,2,1>(patch, out, d2, h2, w1); break;
        default: region_body<2,2,2>(patch, out, d2, h2, w2); break;
    }
}

extern "C" void kernel_launch(void* const* d_in, const int* in_sizes, int n_in,
                              void* d_out, int out_size) {
    const float* patch = (const float*)d_in[0];
    float* out = (float*)d_out;
    dim3 block(24, 8, 1);       // 24 w-groups (96 w) x 8 h rows = 192 threads
    dim3 grid(12, 96, 8);       // 12 h-blocks x 96 d x 8 region classes
    agg_kernel_r8<<<grid, block>>>(patch, out);
}

// round 11
// speedup vs baseline: 1.0309x; 1.0309x over previous
#include <cuda_runtime.h>
#include <cuda_bf16.h>

// DynamicPatchAggregator — gather, float4 along w, full 3-axis region
// specialization with CLASS-INTERLEAVED scheduling: the 8 (nd,nh,nw)
// coverage classes are encoded in the fastest-varying bits of blockIdx.x,
// so every scheduling wave carries a uniform mix of light (2-load) and
// heavy (16-load) blocks -> constant DRAM pressure, no all-heavy tail.
// vol=192^3, patch=96^3, stride=48 -> starts {0,48,96}, 27 patches, C=2.
// Coverage complete -> upsampled global branch contributes 0; skipped.

#define VOL 192
#define PATCH 96
#define STRIDE 48
#define CH_STRIDE (PATCH*PATCH*PATCH)          // 884736
#define PATCH_STRIDE (2*CH_STRIDE)             // per-k stride (C=2)
#define OUT_CH_STRIDE (VOL*VOL*VOL)            // 7077888

__device__ __forceinline__ float gweight(int l) {
    float t = (float)(l - 48) * (1.0f / 12.0f);
    return __expf(-0.5f * t * t);
}

template<int ND, int NH, int NW>
__device__ __forceinline__ void region_body(const float* __restrict__ patch,
                                            float* __restrict__ out,
                                            int d, int h, int w0) {
    // d axis
    const int lod = max((d - 48) / 48, 0);
    const int ld0 = d - lod * STRIDE;
    float gd[2]; int offD[2];
    gd[0]  = gweight(ld0);
    offD[0] = lod * (9 * PATCH_STRIDE) + ld0 * (PATCH * PATCH);
    if (ND == 2) {
        gd[1]  = gweight(ld0 - STRIDE);
        offD[1] = offD[0] + 9 * PATCH_STRIDE - STRIDE * (PATCH * PATCH);
    }

    // h axis
    const int loh = max((h - 48) / 48, 0);
    const int lh0 = h - loh * STRIDE;
    float gh[2]; int offH[2];
    gh[0]  = gweight(lh0);
    offH[0] = loh * (3 * PATCH_STRIDE) + lh0 * PATCH;
    if (NH == 2) {
        gh[1]  = gweight(lh0 - STRIDE);
        offH[1] = offH[0] + 3 * PATCH_STRIDE - STRIDE * PATCH;
    }

    // w axis (compile-time NW)
    const int wlo = max((w0 - 48) / 48, 0);
    const int wl0 = w0 - wlo * STRIDE;
    int offW[2];
    offW[0] = wlo * PATCH_STRIDE + wl0;
    float gw[2][4], gsw[4];
    #pragma unroll
    for (int j = 0; j < 4; j++) {
        gw[0][j] = gweight(wl0 + j);
        gsw[j] = gw[0][j];
    }
    if (NW == 2) {
        offW[1] = offW[0] + PATCH_STRIDE - STRIDE;
        #pragma unroll
        for (int j = 0; j < 4; j++) {
            gw[1][j] = gweight(wl0 - STRIDE + j);
            gsw[j] += gw[1][j];
        }
    }

    float4 acc0 = make_float4(0.f, 0.f, 0.f, 0.f);
    float4 acc1 = make_float4(0.f, 0.f, 0.f, 0.f);

    #pragma unroll
    for (int id = 0; id < ND; id++) {
        #pragma unroll
        for (int ih = 0; ih < NH; ih++) {
            const float gdh = gd[id] * gh[ih];
            const int offDH = offD[id] + offH[ih];
            #pragma unroll
            for (int iw = 0; iw < NW; iw++) {
                const float* q = patch + offDH + offW[iw];
                const float4 v0 = __ldcs(reinterpret_cast<const float4*>(q));
                const float4 v1 = __ldcs(reinterpret_cast<const float4*>(q + CH_STRIDE));
                acc0.x = fmaf(gdh * gw[iw][0], v0.x, acc0.x);
                acc0.y = fmaf(gdh * gw[iw][1], v0.y, acc0.y);
                acc0.z = fmaf(gdh * gw[iw][2], v0.z, acc0.z);
                acc0.w = fmaf(gdh * gw[iw][3], v0.w, acc0.w);
                acc1.x = fmaf(gdh * gw[iw][0], v1.x, acc1.x);
                acc1.y = fmaf(gdh * gw[iw][1], v1.y, acc1.y);
                acc1.z = fmaf(gdh * gw[iw][2], v1.z, acc1.z);
                acc1.w = fmaf(gdh * gw[iw][3], v1.w, acc1.w);
            }
        }
    }

    const float gdsum = (ND == 2) ? gd[0] + gd[1] : gd[0];
    const float ghsum = (NH == 2) ? gh[0] + gh[1] : gh[0];
    const float gdsh = gdsum * ghsum;
    float4 inv;
    inv.x = __frcp_rn(fmaf(gdsh, gsw[0], 1e-20f));
    inv.y = __frcp_rn(fmaf(gdsh, gsw[1], 1e-20f));
    inv.z = __frcp_rn(fmaf(gdsh, gsw[2], 1e-20f));
    inv.w = __frcp_rn(fmaf(gdsh, gsw[3], 1e-20f));

    acc0.x *= inv.x; acc0.y *= inv.y; acc0.z *= inv.z; acc0.w *= inv.w;
    acc1.x *= inv.x; acc1.y *= inv.y; acc1.z *= inv.z; acc1.w *= inv.w;

    const int vidx = (d * VOL + h) * VOL + w0;
    __stcs(reinterpret_cast<float4*>(out + vidx), acc0);
    __stcs(reinterpret_cast<float4*>(out + vidx + OUT_CH_STRIDE), acc1);
}

__global__ __launch_bounds__(192, 6) void agg_kernel_ri(const float* __restrict__ patch,
                                                        float* __restrict__ out) {
    const int cls = blockIdx.x & 7;                 // fastest-varying: class mix per wave
    const int hb  = blockIdx.x >> 3;                // 0..11
    const int wr = threadIdx.x * 4;                 // 0..92 region-local w
    const int hr = hb * 8 + threadIdx.y;            // 0..95 region-local h
    const int dr = blockIdx.y;                      // 0..95 region-local d

    // class-1 (single-cover) coords: [0,48)u[144,192); class-2: [48,144)
    const int w1 = (wr < 48) ? wr : wr + 96;
    const int h1 = (hr < 48) ? hr : hr + 96;
    const int d1 = (dr < 48) ? dr : dr + 96;
    const int w2 = wr + 48, h2 = hr + 48, d2 = dr + 48;

    switch (cls) {
        case 0: region_body<1,1,1>(patch, out, d1, h1, w1); break;
        case 1: region_body<2,2,2>(patch, out, d2, h2, w2); break;
        case 2: region_body<1,2,1>(patch, out, d1, h2, w1); break;
        case 3: region_body<2,1,2>(patch, out, d2, h1, w2); break;
        case 4: region_body<2,1,1>(patch, out, d2, h1, w1); break;
        case 5: region_body<1,2,2>(patch, out, d1, h2, w2); break;
        case 6: region_body<2,2,1>(patch, out, d2, h2, w1); break;
        default: region_body<1,1,2>(patch, out, d1, h1, w2); break;
    }
}

extern "C" void kernel_launch(void* const* d_in, const int* in_sizes, int n_in,
                              void* d_out, int out_size) {
    const float* patch = (const float*)d_in[0];
    float* out = (float*)d_out;
    dim3 block(24, 8, 1);       // 24 w-groups (96 w) x 8 h rows = 192 threads
    dim3 grid(96, 96, 1);       // (12 h-blocks x 8 classes) x 96 d
    agg_kernel_ri<<<grid, block>>>(patch, out);
}